// round 15
// baseline (speedup 1.0000x reference)
#include <cuda_runtime.h>
#include <cuda_bf16.h>
#include <cstddef>
#include <cstdint>

typedef unsigned long long ull;

// ---------------------------------------------------------------------------
// Scratch (static device memory — no allocations anywhere)
// ---------------------------------------------------------------------------
__device__ float g_x4[32u * 128u * 256u];        // flat (32, 32768)
__device__ float g_p0[8192u * 3u * 32u * 32u];
__device__ float g_p1[2048u * 3u * 32u * 64u];
__device__ float g_p2[512u  * 3u * 3u * 32u * 128u];
__device__ float g_p3[128u  * 3u * 3u * 32u * 256u];
__device__ float g_pf[64u * 32u * 512u];
__device__ float g_h[32u * 512u];
// bf16 hi/lo activations
__device__ __nv_bfloat16 g_x0h[32768u * 3u * 32u];   // transposed input (V,3,B)
__device__ __nv_bfloat16 g_x0l[32768u * 3u * 32u];
__device__ __nv_bfloat16 g_x1h[32u * 8192u * 32u];
__device__ __nv_bfloat16 g_x1l[32u * 8192u * 32u];
__device__ __nv_bfloat16 g_x2h[32u * 2048u * 64u];
__device__ __nv_bfloat16 g_x2l[32u * 2048u * 64u];
__device__ __nv_bfloat16 g_x3h[32u * 512u * 128u];
__device__ __nv_bfloat16 g_x3l[32u * 512u * 128u];
// bf16 hi/lo transposed (padded) weights Wt[n][j]
__device__ __nv_bfloat16 g_w0h[32u * 48u],   g_w0l[32u * 48u];
__device__ __nv_bfloat16 g_w1h[64u * 384u],  g_w1l[64u * 384u];
__device__ __nv_bfloat16 g_w2h[128u * 768u], g_w2l[128u * 768u];
__device__ __nv_bfloat16 g_w3h[256u * 1536u],g_w3l[256u * 1536u];

// ---------------------------------------------------------------------------
// helpers
// ---------------------------------------------------------------------------
__device__ __forceinline__ ull pack2(float lo, float hi) {
    ull r; asm("mov.b64 %0, {%1, %2};" : "=l"(r) : "f"(lo), "f"(hi)); return r;
}
__device__ __forceinline__ void unpack2(ull v, float& lo, float& hi) {
    asm("mov.b64 {%0, %1}, %2;" : "=f"(lo), "=f"(hi) : "l"(v));
}
__device__ __forceinline__ void fma2(ull& d, ull a, ull b) {
    asm("fma.rn.f32x2 %0, %1, %2, %0;" : "+l"(d) : "l"(a), "l"(b));
}
__device__ __forceinline__ float elu_f(float a) {
    return (a > 0.f) ? a : (__expf(a) - 1.f);
}
__device__ __forceinline__ uint32_t smem_u32(const void* p) {
    uint32_t a;
    asm("{ .reg .u64 t; cvta.to.shared.u64 t, %1; cvt.u32.u64 %0, t; }" : "=r"(a) : "l"(p));
    return a;
}
__device__ __forceinline__ void mma_bf16(float* c, const uint32_t* a,
                                         uint32_t b0, uint32_t b1) {
    asm volatile(
        "mma.sync.aligned.m16n8k16.row.col.f32.bf16.bf16.f32 "
        "{%0,%1,%2,%3}, {%4,%5,%6,%7}, {%8,%9}, {%0,%1,%2,%3};"
        : "+f"(c[0]), "+f"(c[1]), "+f"(c[2]), "+f"(c[3])
        : "r"(a[0]), "r"(a[1]), "r"(a[2]), "r"(a[3]), "r"(b0), "r"(b1));
}
__device__ __forceinline__ void ldsm_x4(uint32_t* r, uint32_t addr) {
    asm volatile("ldmatrix.sync.aligned.m8n8.x4.shared.b16 {%0,%1,%2,%3}, [%4];"
        : "=r"(r[0]), "=r"(r[1]), "=r"(r[2]), "=r"(r[3]) : "r"(addr));
}
__device__ __forceinline__ void ldsm_x2(uint32_t* r, uint32_t addr) {
    asm volatile("ldmatrix.sync.aligned.m8n8.x2.shared.b16 {%0,%1}, [%2];"
        : "=r"(r[0]), "=r"(r[1]) : "r"(addr));
}
__device__ __forceinline__ void write_bf4(__nv_bfloat16* xh, __nv_bfloat16* xl,
                                          size_t off, float4 o) {
    const __nv_bfloat16 h0 = __float2bfloat16(o.x), h1 = __float2bfloat16(o.y);
    const __nv_bfloat16 h2 = __float2bfloat16(o.z), h3 = __float2bfloat16(o.w);
    *(__nv_bfloat162*)&xh[off]     = __nv_bfloat162(h0, h1);
    *(__nv_bfloat162*)&xh[off + 2] = __nv_bfloat162(h2, h3);
    *(__nv_bfloat162*)&xl[off] = __nv_bfloat162(
        __float2bfloat16(o.x - __bfloat162float(h0)),
        __float2bfloat16(o.y - __bfloat162float(h1)));
    *(__nv_bfloat162*)&xl[off + 2] = __nv_bfloat162(
        __float2bfloat16(o.z - __bfloat162float(h2)),
        __float2bfloat16(o.w - __bfloat162float(h3)));
}

// ---------------------------------------------------------------------------
// W pre-convert + transpose, small/padded variant (stage0 only)
// ---------------------------------------------------------------------------
template<int FANR, int FANP, int COUT>
__global__ void __launch_bounds__(256) conv_wt(
    const float* __restrict__ W, __nv_bfloat16* __restrict__ wh,
    __nv_bfloat16* __restrict__ wl)
{
    const int i = blockIdx.x * 256 + threadIdx.x;
    if (i >= FANP * COUT) return;
    const int n = i % COUT, j = i / COUT;
    float w = 0.f;
    if (j < FANR) w = W[(size_t)j * COUT + n];
    const __nv_bfloat16 h = __float2bfloat16(w);
    wh[(size_t)n * FANP + j] = h;
    wl[(size_t)n * FANP + j] = __float2bfloat16(w - __bfloat162float(h));
}

// ---------------------------------------------------------------------------
// Tiled W transpose (coalesced both sides): Wt[n][j] hi/lo.  FAN % 32 == 0.
// ---------------------------------------------------------------------------
template<int FAN, int COUT>
__global__ void __launch_bounds__(256) conv_wt_t(
    const float* __restrict__ W, __nv_bfloat16* __restrict__ wh,
    __nv_bfloat16* __restrict__ wl)
{
    __shared__ float tile[32][33];
    const int j0 = blockIdx.x * 32;
    const int n0 = blockIdx.y * 32;
    const int tx = threadIdx.x & 31;
    const int ty = threadIdx.x >> 5;
    // read: rows j, coalesced along n
#pragma unroll
    for (int jr = ty; jr < 32; jr += 8)
        tile[jr][tx] = W[(size_t)(j0 + jr) * COUT + n0 + tx];
    __syncthreads();
    // write: rows n, coalesced along j
#pragma unroll
    for (int nr = ty; nr < 32; nr += 8) {
        const float w = tile[tx][nr];
        const __nv_bfloat16 h = __float2bfloat16(w);
        const size_t off = (size_t)(n0 + nr) * FAN + j0 + tx;
        wh[off] = h;
        wl[off] = __float2bfloat16(w - __bfloat162float(h));
    }
}

// ---------------------------------------------------------------------------
// Transpose x (B=32, V, 3) -> bf16 hi/lo (V, 3, 32)
// ---------------------------------------------------------------------------
__global__ void __launch_bounds__(256) transpose_x(
    const float* __restrict__ x,
    __nv_bfloat16* __restrict__ xh, __nv_bfloat16* __restrict__ xl)
{
    __shared__ float smt[96][33];
    const int v0 = blockIdx.x * 32;
    const int t  = threadIdx.x;
    for (int i = t; i < 32 * 96; i += 256) {
        const int b = i / 96, vc = i % 96;
        smt[vc][b] = x[(size_t)b * 98304 + v0 * 3 + vc];
    }
    __syncthreads();
    for (int i = t; i < 96 * 32; i += 256) {
        const int vc = i / 32, b = i % 32;
        const float v = smt[vc][b];
        const __nv_bfloat16 h = __float2bfloat16(v);
        const size_t off = (size_t)(v0 * 3 + vc) * 32 + b;
        xh[off] = h;
        xl[off] = __float2bfloat16(v - __bfloat162float(h));
    }
}

// ---------------------------------------------------------------------------
// Stages 0-3 via mma.sync bf16 hi/lo split (ldmatrix fragment loads).
// 256 threads / 8 warps. CTA tile ROWS x COUT, warp tiling WM x WN, NWN
// warps along n. K-chunks of KCH (KPAD=KCH+8 -> conflict-free ldmatrix).
// CIN==3 uses a scalar gather with zero padding to KPSP*KS.
// ---------------------------------------------------------------------------
template<int CIN, int COUT, int KS, bool SPLITK, int ROWS, int WM, int WN,
         int NWN, int KCH, int KPSP, int FANR>
__global__ void __launch_bounds__(256) stage_hmma(
    const __nv_bfloat16* __restrict__ xh, const __nv_bfloat16* __restrict__ xl,
    const int* __restrict__ spiral, const int* __restrict__ didx,
    const float* __restrict__ dw,
    const __nv_bfloat16* __restrict__ wth, const __nv_bfloat16* __restrict__ wtl,
    const float* __restrict__ bias, float* __restrict__ part,
    int Vin, int vkTiles)
{
    constexpr int S = 12;
    constexpr int FANP = KPSP * KS;
    constexpr int KPAD = KCH + 8;
    constexpr int NCH = KPSP / KCH;
    constexpr int INSTS = ROWS / 32;
    static_assert((8 / NWN) * WM * 16 == ROWS, "");
    static_assert(NWN * WN * 8 == COUT, "");
    static_assert(KPSP % KCH == 0, "");

    extern __shared__ __align__(16) __nv_bfloat16 smb[];
    __nv_bfloat16* Ah = smb;
    __nv_bfloat16* Al = Ah + ROWS * KPAD;
    __nv_bfloat16* Bh = Al + ROWS * KPAD;
    __nv_bfloat16* Bl = Bh + COUT * KPAD;
    __shared__ int   s_sidx[INSTS][S];
    __shared__ float s_wk[INSTS];

    const int t    = threadIdx.x;
    const int wid  = t >> 5;
    const int lane = t & 31;
    const int bs   = blockIdx.x;
    const int ksBlk = SPLITK ? (bs / vkTiles) : 0;
    const int vk0   = (SPLITK ? (bs % vkTiles) : bs) * INSTS;

    if (t < INSTS * S) {
        const int i2 = t / S, s = t % S;
        const int vk = vk0 + i2, v = vk / 3, k = vk % 3;
        const int p = didx[v * 3 + k];
        s_sidx[i2][s] = spiral[p * S + s];
        if (s == 0) s_wk[i2] = dw[v * 3 + k];
    }
    __syncthreads();

    float c[WM][WN][4];
#pragma unroll
    for (int mt = 0; mt < WM; ++mt)
#pragma unroll
        for (int nt = 0; nt < WN; ++nt)
#pragma unroll
            for (int i = 0; i < 4; ++i) c[mt][nt][i] = 0.f;

    const int g = lane >> 2, q = lane & 3;
    const int mwIdx = wid / NWN, nwIdx = wid % NWN;
    const int R0 = mwIdx * WM * 16;
    const int N0 = nwIdx * WN * 8;
    const size_t VinCIN = (size_t)Vin * CIN;

    constexpr uint32_t AL_OFF = (uint32_t)(ROWS * KPAD * 2);
    constexpr uint32_t BL_OFF = (uint32_t)(COUT * KPAD * 2);
    const uint32_t aBase = smem_u32(Ah) +
        ((uint32_t)(R0 + (lane & 15)) * KPAD) * 2 + ((uint32_t)(lane >> 4)) * 16;
    const uint32_t bBase = smem_u32(Bh) +
        ((uint32_t)(N0 + (lane & 7)) * KPAD) * 2 + ((uint32_t)((lane >> 3) & 1)) * 16;

    for (int ch = 0; ch < NCH; ++ch) {
        const int k0 = ksBlk * KPSP + ch * KCH;
        // ---- gather A (ROWS x KCH) ----
        if constexpr (CIN == 3) {
            for (int idx = t; idx < ROWS * KCH; idx += 256) {
                const int r = idx & (ROWS - 1), jj = idx / ROWS;
                const int j = k0 + jj;
                __nv_bfloat16 h(0.f), l(0.f);
                if (j < FANR) {
                    const int s = j / 3, ci = j - s * 3;
                    const int inst = r >> 5, b = r & 31;
                    const size_t off = ((size_t)s_sidx[inst][s] * 3 + ci) * 32 + b;
                    h = xh[off]; l = xl[off];
                }
                Ah[r * KPAD + jj] = h;
                Al[r * KPAD + jj] = l;
            }
        } else {
            const int jp = t & 31;
            const int j  = k0 + jp * 2;
            const int s  = j / CIN;
            const int ci = j % CIN;
            for (int r = t >> 5; r < ROWS; r += 8) {
                const int inst = r >> 5, b = r & 31;
                const size_t off = (size_t)b * VinCIN + (size_t)s_sidx[inst][s] * CIN + ci;
                *(uint32_t*)&Ah[r * KPAD + jp * 2] = *(const uint32_t*)&xh[off];
                *(uint32_t*)&Al[r * KPAD + jp * 2] = *(const uint32_t*)&xl[off];
            }
        }
        // ---- stage B (COUT x KCH) from pre-transposed (padded) weights ----
        {
            constexpr int NP = KCH / 2;
            for (int idx = t; idx < COUT * NP; idx += 256) {
                const int jp = idx % NP, n = idx / NP;
                const size_t off = (size_t)n * FANP + k0 + jp * 2;
                *(uint32_t*)&Bh[n * KPAD + jp * 2] = *(const uint32_t*)&wth[off];
                *(uint32_t*)&Bl[n * KPAD + jp * 2] = *(const uint32_t*)&wtl[off];
            }
        }
        __syncthreads();

#pragma unroll
        for (int kk = 0; kk < KCH; kk += 16) {
            const uint32_t kb = (uint32_t)kk * 2;
            uint32_t ah[WM][4], al[WM][4];
#pragma unroll
            for (int mt = 0; mt < WM; ++mt) {
                const uint32_t ad = aBase + (uint32_t)(mt * 16 * KPAD * 2) + kb;
                ldsm_x4(ah[mt], ad);
                ldsm_x4(al[mt], ad + AL_OFF);
            }
#pragma unroll
            for (int nt = 0; nt < WN; ++nt) {
                const uint32_t bd = bBase + (uint32_t)(nt * 8 * KPAD * 2) + kb;
                uint32_t bh[2], bl[2];
                ldsm_x2(bh, bd);
                ldsm_x2(bl, bd + BL_OFF);
#pragma unroll
                for (int mt = 0; mt < WM; ++mt) {
                    mma_bf16(c[mt][nt], ah[mt], bh[0], bh[1]);
                    mma_bf16(c[mt][nt], al[mt], bh[0], bh[1]);
                    mma_bf16(c[mt][nt], ah[mt], bl[0], bl[1]);
                }
            }
        }
        __syncthreads();
    }

    // ---- epilogue: fragment -> gmem partials ----
#pragma unroll
    for (int mt = 0; mt < WM; ++mt) {
        const int rBase = R0 + mt * 16;
        const int inst  = rBase >> 5;
        const int vk    = vk0 + inst;
        const float wk  = s_wk[inst];
        const int rA = rBase + g, rB = rA + 8;
        size_t baseA, baseB;
        if (SPLITK) {
            const size_t vb = ((size_t)vk * KS + ksBlk) * 32;
            baseA = (vb + (rA & 31)) * COUT;
            baseB = (vb + (rB & 31)) * COUT;
        } else {
            baseA = ((size_t)vk * 32 + (rA & 31)) * COUT;
            baseB = ((size_t)vk * 32 + (rB & 31)) * COUT;
        }
#pragma unroll
        for (int nt = 0; nt < WN; ++nt) {
            const int col = N0 + nt * 8 + q * 2;
            float v0 = c[mt][nt][0], v1 = c[mt][nt][1];
            float v2 = c[mt][nt][2], v3 = c[mt][nt][3];
            if (!SPLITK) {
                const float bi0 = bias[col], bi1 = bias[col + 1];
                v0 = wk * elu_f(v0 + bi0); v1 = wk * elu_f(v1 + bi1);
                v2 = wk * elu_f(v2 + bi0); v3 = wk * elu_f(v3 + bi1);
            }
            *(float2*)&part[baseA + col] = make_float2(v0, v1);
            *(float2*)&part[baseB + col] = make_float2(v2, v3);
        }
    }
}

// ---------------------------------------------------------------------------
// Pool-reduce; writes fp32 and/or bf16 hi/lo per flags
// ---------------------------------------------------------------------------
template<int COUT, bool WF32, bool BF>
__global__ void reduce_pool(const float* __restrict__ part,
                            float* __restrict__ xout,
                            __nv_bfloat16* __restrict__ xh,
                            __nv_bfloat16* __restrict__ xl,
                            int Vout, int total4)
{
    const int i = blockIdx.x * 256 + threadIdx.x;
    if (i >= total4) return;
    constexpr int C4 = COUT / 4;
    const int c4 = i % C4;
    const int v  = (i / C4) % Vout;
    const int b  = i / (C4 * Vout);
    const float4* p = (const float4*)part;
    float4 a0 = p[((size_t)(v * 3 + 0) * 32 + b) * C4 + c4];
    float4 a1 = p[((size_t)(v * 3 + 1) * 32 + b) * C4 + c4];
    float4 a2 = p[((size_t)(v * 3 + 2) * 32 + b) * C4 + c4];
    const float4 o = make_float4(a0.x + a1.x + a2.x, a0.y + a1.y + a2.y,
                                 a0.z + a1.z + a2.z, a0.w + a1.w + a2.w);
    const size_t off4 = ((size_t)b * Vout + v) * C4 + c4;
    if constexpr (WF32) ((float4*)xout)[off4] = o;
    if constexpr (BF)   write_bf4(xh, xl, off4 * 4, o);
}

// ---------------------------------------------------------------------------
// K-split reduce: bias + ELU + dw + pool; outputs per flags
// ---------------------------------------------------------------------------
template<int COUT, int KS, bool WF32, bool BF>
__global__ void reduce_split(const float* __restrict__ part,
                             const float* __restrict__ dw,
                             const float* __restrict__ bias,
                             float* __restrict__ xout,
                             __nv_bfloat16* __restrict__ xh,
                             __nv_bfloat16* __restrict__ xl,
                             int Vout, int total4)
{
    const int i = blockIdx.x * 256 + threadIdx.x;
    if (i >= total4) return;
    constexpr int C4 = COUT / 4;
    const int c4 = i % C4;
    const int v  = (i / C4) % Vout;
    const int b  = i / (C4 * Vout);
    const float4* p = (const float4*)part;
    const float4 bs4 = ((const float4*)bias)[c4];
    float4 o = make_float4(0.f, 0.f, 0.f, 0.f);
#pragma unroll
    for (int k = 0; k < 3; ++k) {
        float4 s = bs4;
#pragma unroll
        for (int ks = 0; ks < KS; ++ks) {
            const float4 a = p[(((size_t)(v * 3 + k) * KS + ks) * 32 + b) * C4 + c4];
            s.x += a.x; s.y += a.y; s.z += a.z; s.w += a.w;
        }
        const float wk = dw[v * 3 + k];
        o.x += wk * elu_f(s.x);
        o.y += wk * elu_f(s.y);
        o.z += wk * elu_f(s.z);
        o.w += wk * elu_f(s.w);
    }
    const size_t off4 = ((size_t)b * Vout + v) * C4 + c4;
    if constexpr (WF32) ((float4*)xout)[off4] = o;
    if constexpr (BF)   write_bf4(xh, xl, off4 * 4, o);
}

// ---------------------------------------------------------------------------
// FC1 partial GEMM + reduce + FC2 (round-7, proven)
// ---------------------------------------------------------------------------
__global__ void __launch_bounds__(256, 2) fc1_conv(
    const float* __restrict__ xf, const float* __restrict__ Wl1,
    float* __restrict__ partf)
{
    constexpr int KC = 64, CT = 256, LANES = 64, GSROW = 34;
    extern __shared__ float sm[];
    float* Ws = sm;
    float* xs = sm + KC * CT;

    const int t = threadIdx.x;
    const int tx = t % LANES, pg = t / LANES;
    const int ct0 = blockIdx.x * CT;
    const int k0 = blockIdx.y * 512;

    ull acc[4][4];
#pragma unroll
    for (int ic = 0; ic < 4; ++ic)
#pragma unroll
        for (int ibp = 0; ibp < 4; ++ibp) acc[ic][ibp] = 0ull;

    for (int kc = 0; kc < 512; kc += KC) {
        const int kk0 = k0 + kc;
        for (int i = t; i < KC * CT / 4; i += 256) {
            const int row = i / (CT / 4), col = i % (CT / 4);
            ((float4*)Ws)[i] = *(const float4*)&Wl1[(size_t)(kk0 + row) * 512 + ct0 + col * 4];
        }
#pragma unroll
        for (int e = 0; e < 8; ++e) {
            const int idx = e * 256 + t;
            const int b = idx / KC, jj = idx % KC;
            xs[jj * GSROW + b] = xf[(size_t)b * 32768 + kk0 + jj];
        }
        __syncthreads();

        const float* gb = xs + pg * 8;
#pragma unroll 4
        for (int jj = 0; jj < KC; ++jj) {
            const float4 w4 = *(const float4*)&Ws[jj * CT + tx * 4];
            ull wp[4];
            wp[0] = pack2(w4.x, w4.x);
            wp[1] = pack2(w4.y, w4.y);
            wp[2] = pack2(w4.z, w4.z);
            wp[3] = pack2(w4.w, w4.w);
            ull gp[4];
#pragma unroll
            for (int ibp = 0; ibp < 4; ++ibp)
                gp[ibp] = *(const ull*)&gb[jj * GSROW + 2 * ibp];
#pragma unroll
            for (int ic = 0; ic < 4; ++ic)
#pragma unroll
                for (int ibp = 0; ibp < 4; ++ibp)
                    fma2(acc[ic][ibp], gp[ibp], wp[ic]);
        }
        __syncthreads();
    }

    const size_t base = (size_t)blockIdx.y * 32 * 512 + ct0 + tx * 4;
#pragma unroll
    for (int ibp = 0; ibp < 4; ++ibp) {
        const int b0 = (pg * 4 + ibp) * 2;
        float lo[4], hi[4];
#pragma unroll
        for (int ic = 0; ic < 4; ++ic) unpack2(acc[ic][ibp], lo[ic], hi[ic]);
        *(float4*)&partf[base + (size_t)b0 * 512]       = make_float4(lo[0], lo[1], lo[2], lo[3]);
        *(float4*)&partf[base + (size_t)(b0 + 1) * 512] = make_float4(hi[0], hi[1], hi[2], hi[3]);
    }
}

__global__ void fc1_reduce(const float* __restrict__ partf,
                           const float* __restrict__ bl1,
                           float* __restrict__ h, float* __restrict__ out)
{
    const int i = blockIdx.x * 256 + threadIdx.x;
    if (i < 16384) {
        float s = 0.f;
#pragma unroll
        for (int p = 0; p < 64; ++p) s += partf[p * 16384 + i];
        s += bl1[i & 511];
        s = elu_f(s);
        h[i] = s;
        out[i] = s;
    }
}

__global__ void fc2_kernel(const float* __restrict__ h,
                           const float* __restrict__ Wl2,
                           const float* __restrict__ bl2,
                           float* __restrict__ out)
{
    const int b = blockIdx.x;
    const int c = threadIdx.x;
    float acc = bl2[c];
    for (int k = 0; k < 512; ++k)
        acc = fmaf(h[b * 512 + k], Wl2[k * 64 + c], acc);
    out[16384 + b * 64 + c] = acc;
}

// ---------------------------------------------------------------------------
// Host launcher
// ---------------------------------------------------------------------------
extern "C" void kernel_launch(void* const* d_in, const int* in_sizes, int n_in,
                              void* d_out, int out_size)
{
    int I_sp[4], I_di[4], I_dw[4], I_W[4], I_b[4];
    if (in_sizes[2] == 8192 * 3) {           // dict order
        for (int i = 0; i < 4; ++i) {
            I_sp[i] = 1 + 5 * i; I_di[i] = 2 + 5 * i; I_dw[i] = 3 + 5 * i;
            I_W[i] = 4 + 5 * i;  I_b[i] = 5 + 5 * i;
        }
    } else {                                  // signature order
        for (int i = 0; i < 4; ++i) {
            I_sp[i] = 1 + i; I_di[i] = 5 + i; I_dw[i] = 9 + i;
            I_W[i] = 13 + 2 * i; I_b[i] = 14 + 2 * i;
        }
    }

    const float* x = (const float*)d_in[0];
    const int* sp[4]; const int* di[4]; const float* dwp[4];
    const float* W[4]; const float* b[4];
    for (int i = 0; i < 4; ++i) {
        sp[i]  = (const int*)  d_in[I_sp[i]];
        di[i]  = (const int*)  d_in[I_di[i]];
        dwp[i] = (const float*)d_in[I_dw[i]];
        W[i]   = (const float*)d_in[I_W[i]];
        b[i]   = (const float*)d_in[I_b[i]];
    }
    const float* Wl1 = (const float*)d_in[21];
    const float* bl1 = (const float*)d_in[22];
    const float* Wl2 = (const float*)d_in[23];
    const float* bl2 = (const float*)d_in[24];

    float *x4, *p0, *p1, *p2, *p3, *pf, *h;
    __nv_bfloat16 *x0h, *x0l, *x1h, *x1l, *x2h, *x2l, *x3h, *x3l;
    __nv_bfloat16 *w0h, *w0l, *w1h, *w1l, *w2h, *w2l, *w3h, *w3l;
    cudaGetSymbolAddress((void**)&x4, g_x4);
    cudaGetSymbolAddress((void**)&p0, g_p0);
    cudaGetSymbolAddress((void**)&p1, g_p1);
    cudaGetSymbolAddress((void**)&p2, g_p2);
    cudaGetSymbolAddress((void**)&p3, g_p3);
    cudaGetSymbolAddress((void**)&pf, g_pf);
    cudaGetSymbolAddress((void**)&h,  g_h);
    cudaGetSymbolAddress((void**)&x0h, g_x0h);
    cudaGetSymbolAddress((void**)&x0l, g_x0l);
    cudaGetSymbolAddress((void**)&x1h, g_x1h);
    cudaGetSymbolAddress((void**)&x1l, g_x1l);
    cudaGetSymbolAddress((void**)&x2h, g_x2h);
    cudaGetSymbolAddress((void**)&x2l, g_x2l);
    cudaGetSymbolAddress((void**)&x3h, g_x3h);
    cudaGetSymbolAddress((void**)&x3l, g_x3l);
    cudaGetSymbolAddress((void**)&w0h, g_w0h);
    cudaGetSymbolAddress((void**)&w0l, g_w0l);
    cudaGetSymbolAddress((void**)&w1h, g_w1h);
    cudaGetSymbolAddress((void**)&w1l, g_w1l);
    cudaGetSymbolAddress((void**)&w2h, g_w2h);
    cudaGetSymbolAddress((void**)&w2l, g_w2l);
    cudaGetSymbolAddress((void**)&w3h, g_w3h);
    cudaGetSymbolAddress((void**)&w3l, g_w3l);
    float* out = (float*)d_out;

    // smem bytes: 2*(ROWS*KPAD + COUT*KPAD)*2
    const int smH0 = 2 * (128 * 56 + 32 * 56) * 2;                // 35840
    const int smH1 = 2 * (256 * 72 + 64 * 72) * 2;                // 92160
    const int smH2 = 2 * (128 * 72 + 128 * 72) * 2;               // 73728
    const int smH3 = 2 * (64 * 72 + 256 * 72) * 2;                // 92160
    const int smf  = (64 * 256 + 64 * 34) * 4;                    // 74240

    cudaFuncSetAttribute(stage_hmma<3, 32, 1, false, 128, 1, 4, 1, 48, 48, 36>,
                         cudaFuncAttributeMaxDynamicSharedMemorySize, smH0);
    cudaFuncSetAttribute(stage_hmma<32, 64, 1, false, 256, 4, 4, 2, 64, 384, 384>,
                         cudaFuncAttributeMaxDynamicSharedMemorySize, smH1);
    cudaFuncSetAttribute(stage_hmma<64, 128, 3, true, 128, 4, 4, 4, 64, 256, 768>,
                         cudaFuncAttributeMaxDynamicSharedMemorySize, smH2);
    cudaFuncSetAttribute(stage_hmma<128, 256, 3, true, 64, 4, 4, 8, 64, 512, 1536>,
                         cudaFuncAttributeMaxDynamicSharedMemorySize, smH3);
    cudaFuncSetAttribute(fc1_conv, cudaFuncAttributeMaxDynamicSharedMemorySize, smf);

    // weight pre-convert (tiled, coalesced)
    conv_wt<36, 48, 32><<<6, 256>>>(W[0], w0h, w0l);
    conv_wt_t<384, 64><<<dim3(12, 2), 256>>>(W[1], w1h, w1l);
    conv_wt_t<768, 128><<<dim3(24, 4), 256>>>(W[2], w2h, w2l);
    conv_wt_t<1536, 256><<<dim3(48, 8), 256>>>(W[3], w3h, w3l);

    transpose_x<<<1024, 256>>>(x, x0h, x0l);

    // stage0 (HMMA): vk=24576, 4 inst/CTA -> 6144 CTAs
    stage_hmma<3, 32, 1, false, 128, 1, 4, 1, 48, 48, 36><<<6144, 256, smH0>>>(
        x0h, x0l, sp[0], di[0], dwp[0], w0h, w0l, b[0], p0, 32768, 6144);
    reduce_pool<32, false, true><<<8192, 256>>>(p0, nullptr, x1h, x1l, 8192, 32 * 8192 * 8);

    // stage1 (HMMA): vk=6144, 8 inst/CTA -> 768 CTAs
    stage_hmma<32, 64, 1, false, 256, 4, 4, 2, 64, 384, 384><<<768, 256, smH1>>>(
        x1h, x1l, sp[1], di[1], dwp[1], w1h, w1l, b[1], p1, 8192, 768);
    reduce_pool<64, false, true><<<4096, 256>>>(p1, nullptr, x2h, x2l, 2048, 32 * 2048 * 16);

    // stage2 (HMMA): vk=1536, 4 inst/CTA -> 384 tiles x 3 KS = 1152 CTAs
    stage_hmma<64, 128, 3, true, 128, 4, 4, 4, 64, 256, 768><<<1152, 256, smH2>>>(
        x2h, x2l, sp[2], di[2], dwp[2], w2h, w2l, b[2], p2, 2048, 384);
    reduce_split<128, 3, false, true><<<2048, 256>>>(p2, dwp[2], b[2], nullptr, x3h, x3l, 512, 32 * 512 * 32);

    // stage3 (HMMA): vk=384, 2 inst/CTA -> 192 tiles x 3 KS = 576 CTAs
    stage_hmma<128, 256, 3, true, 64, 4, 4, 8, 64, 512, 1536><<<576, 256, smH3>>>(
        x3h, x3l, sp[3], di[3], dwp[3], w3h, w3l, b[3], p3, 512, 192);
    reduce_split<256, 3, true, false><<<1024, 256>>>(p3, dwp[3], b[3], x4, nullptr, nullptr, 128, 32 * 128 * 64);

    fc1_conv<<<dim3(2, 64), 256, smf>>>(x4, Wl1, pf);
    fc1_reduce<<<64, 256>>>(pf, bl1, h, out);
    fc2_kernel<<<32, 64>>>(h, Wl2, bl2, out);
}

// round 16
// speedup vs baseline: 1.4682x; 1.4682x over previous
#include <cuda_runtime.h>
#include <cuda_bf16.h>
#include <cstddef>
#include <cstdint>

typedef unsigned long long ull;

// ---------------------------------------------------------------------------
// Scratch (static device memory — no allocations anywhere)
// ---------------------------------------------------------------------------
__device__ float g_x4[32u * 128u * 256u];        // flat (32, 32768)
__device__ float g_p0[8192u * 3u * 32u * 32u];
__device__ float g_p1[2048u * 3u * 32u * 64u];
__device__ float g_p2[512u  * 3u * 3u * 32u * 128u];
__device__ float g_p3[128u  * 3u * 3u * 32u * 256u];
__device__ float g_pf[64u * 32u * 512u];
__device__ float g_h[32u * 512u];
// bf16 hi/lo activations
__device__ __nv_bfloat16 g_x0h[32768u * 3u * 32u];   // transposed input (V,3,B)
__device__ __nv_bfloat16 g_x0l[32768u * 3u * 32u];
__device__ __nv_bfloat16 g_x1h[32u * 8192u * 32u];
__device__ __nv_bfloat16 g_x1l[32u * 8192u * 32u];
__device__ __nv_bfloat16 g_x2h[32u * 2048u * 64u];
__device__ __nv_bfloat16 g_x2l[32u * 2048u * 64u];
__device__ __nv_bfloat16 g_x3h[32u * 512u * 128u];
__device__ __nv_bfloat16 g_x3l[32u * 512u * 128u];
// bf16 hi/lo transposed (padded) weights Wt[n][j]
__device__ __nv_bfloat16 g_w0h[32u * 48u],   g_w0l[32u * 48u];
__device__ __nv_bfloat16 g_w1h[64u * 384u],  g_w1l[64u * 384u];
__device__ __nv_bfloat16 g_w2h[128u * 768u], g_w2l[128u * 768u];
__device__ __nv_bfloat16 g_w3h[256u * 1536u],g_w3l[256u * 1536u];

// ---------------------------------------------------------------------------
// helpers
// ---------------------------------------------------------------------------
__device__ __forceinline__ ull pack2(float lo, float hi) {
    ull r; asm("mov.b64 %0, {%1, %2};" : "=l"(r) : "f"(lo), "f"(hi)); return r;
}
__device__ __forceinline__ void unpack2(ull v, float& lo, float& hi) {
    asm("mov.b64 {%0, %1}, %2;" : "=f"(lo), "=f"(hi) : "l"(v));
}
__device__ __forceinline__ void fma2(ull& d, ull a, ull b) {
    asm("fma.rn.f32x2 %0, %1, %2, %0;" : "+l"(d) : "l"(a), "l"(b));
}
__device__ __forceinline__ float elu_f(float a) {
    return (a > 0.f) ? a : (__expf(a) - 1.f);
}
__device__ __forceinline__ uint32_t smem_u32(const void* p) {
    uint32_t a;
    asm("{ .reg .u64 t; cvta.to.shared.u64 t, %1; cvt.u32.u64 %0, t; }" : "=r"(a) : "l"(p));
    return a;
}
__device__ __forceinline__ void mma_bf16(float* c, const uint32_t* a,
                                         uint32_t b0, uint32_t b1) {
    asm volatile(
        "mma.sync.aligned.m16n8k16.row.col.f32.bf16.bf16.f32 "
        "{%0,%1,%2,%3}, {%4,%5,%6,%7}, {%8,%9}, {%0,%1,%2,%3};"
        : "+f"(c[0]), "+f"(c[1]), "+f"(c[2]), "+f"(c[3])
        : "r"(a[0]), "r"(a[1]), "r"(a[2]), "r"(a[3]), "r"(b0), "r"(b1));
}
__device__ __forceinline__ void ldsm_x4(uint32_t* r, uint32_t addr) {
    asm volatile("ldmatrix.sync.aligned.m8n8.x4.shared.b16 {%0,%1,%2,%3}, [%4];"
        : "=r"(r[0]), "=r"(r[1]), "=r"(r[2]), "=r"(r[3]) : "r"(addr));
}
__device__ __forceinline__ void ldsm_x2(uint32_t* r, uint32_t addr) {
    asm volatile("ldmatrix.sync.aligned.m8n8.x2.shared.b16 {%0,%1}, [%2];"
        : "=r"(r[0]), "=r"(r[1]) : "r"(addr));
}
__device__ __forceinline__ void write_bf4(__nv_bfloat16* xh, __nv_bfloat16* xl,
                                          size_t off, float4 o) {
    const __nv_bfloat16 h0 = __float2bfloat16(o.x), h1 = __float2bfloat16(o.y);
    const __nv_bfloat16 h2 = __float2bfloat16(o.z), h3 = __float2bfloat16(o.w);
    *(__nv_bfloat162*)&xh[off]     = __nv_bfloat162(h0, h1);
    *(__nv_bfloat162*)&xh[off + 2] = __nv_bfloat162(h2, h3);
    *(__nv_bfloat162*)&xl[off] = __nv_bfloat162(
        __float2bfloat16(o.x - __bfloat162float(h0)),
        __float2bfloat16(o.y - __bfloat162float(h1)));
    *(__nv_bfloat162*)&xl[off + 2] = __nv_bfloat162(
        __float2bfloat16(o.z - __bfloat162float(h2)),
        __float2bfloat16(o.w - __bfloat162float(h3)));
}

// ---------------------------------------------------------------------------
// W pre-convert + transpose, small/padded variant (stage0 only)
// ---------------------------------------------------------------------------
template<int FANR, int FANP, int COUT>
__global__ void __launch_bounds__(256) conv_wt(
    const float* __restrict__ W, __nv_bfloat16* __restrict__ wh,
    __nv_bfloat16* __restrict__ wl)
{
    const int i = blockIdx.x * 256 + threadIdx.x;
    if (i >= FANP * COUT) return;
    const int n = i % COUT, j = i / COUT;
    float w = 0.f;
    if (j < FANR) w = W[(size_t)j * COUT + n];
    const __nv_bfloat16 h = __float2bfloat16(w);
    wh[(size_t)n * FANP + j] = h;
    wl[(size_t)n * FANP + j] = __float2bfloat16(w - __bfloat162float(h));
}

// ---------------------------------------------------------------------------
// Tiled W transpose (coalesced both sides): Wt[n][j] hi/lo.  FAN % 32 == 0.
// ---------------------------------------------------------------------------
template<int FAN, int COUT>
__global__ void __launch_bounds__(256) conv_wt_t(
    const float* __restrict__ W, __nv_bfloat16* __restrict__ wh,
    __nv_bfloat16* __restrict__ wl)
{
    __shared__ float tile[32][33];
    const int j0 = blockIdx.x * 32;
    const int n0 = blockIdx.y * 32;
    const int tx = threadIdx.x & 31;
    const int ty = threadIdx.x >> 5;
#pragma unroll
    for (int jr = ty; jr < 32; jr += 8)
        tile[jr][tx] = W[(size_t)(j0 + jr) * COUT + n0 + tx];
    __syncthreads();
#pragma unroll
    for (int nr = ty; nr < 32; nr += 8) {
        const float w = tile[tx][nr];
        const __nv_bfloat16 h = __float2bfloat16(w);
        const size_t off = (size_t)(n0 + nr) * FAN + j0 + tx;
        wh[off] = h;
        wl[off] = __float2bfloat16(w - __bfloat162float(h));
    }
}

// ---------------------------------------------------------------------------
// Transpose x (B=32, V, 3) -> bf16 hi/lo (V, 3, 32)
// ---------------------------------------------------------------------------
__global__ void __launch_bounds__(256) transpose_x(
    const float* __restrict__ x,
    __nv_bfloat16* __restrict__ xh, __nv_bfloat16* __restrict__ xl)
{
    __shared__ float smt[96][33];
    const int v0 = blockIdx.x * 32;
    const int t  = threadIdx.x;
    for (int i = t; i < 32 * 96; i += 256) {
        const int b = i / 96, vc = i % 96;
        smt[vc][b] = x[(size_t)b * 98304 + v0 * 3 + vc];
    }
    __syncthreads();
    for (int i = t; i < 96 * 32; i += 256) {
        const int vc = i / 32, b = i % 32;
        const float v = smt[vc][b];
        const __nv_bfloat16 h = __float2bfloat16(v);
        const size_t off = (size_t)(v0 * 3 + vc) * 32 + b;
        xh[off] = h;
        xl[off] = __float2bfloat16(v - __bfloat162float(h));
    }
}

// ---------------------------------------------------------------------------
// Stages 0-3 via mma.sync bf16 hi/lo split (ldmatrix fragment loads).
// 256 threads / 8 warps. CTA tile ROWS x COUT, warp tiling WM x WN, NWN
// warps along n. K-chunks of KCH (KPAD=KCH+8 -> conflict-free ldmatrix).
// CIN==3 uses a scalar gather with zero padding to KPSP*KS.
// ---------------------------------------------------------------------------
template<int CIN, int COUT, int KS, bool SPLITK, int ROWS, int WM, int WN,
         int NWN, int KCH, int KPSP, int FANR>
__global__ void __launch_bounds__(256) stage_hmma(
    const __nv_bfloat16* __restrict__ xh, const __nv_bfloat16* __restrict__ xl,
    const int* __restrict__ spiral, const int* __restrict__ didx,
    const float* __restrict__ dw,
    const __nv_bfloat16* __restrict__ wth, const __nv_bfloat16* __restrict__ wtl,
    const float* __restrict__ bias, float* __restrict__ part,
    int Vin, int vkTiles)
{
    constexpr int S = 12;
    constexpr int FANP = KPSP * KS;
    constexpr int KPAD = KCH + 8;
    constexpr int NCH = KPSP / KCH;
    constexpr int INSTS = ROWS / 32;
    static_assert((8 / NWN) * WM * 16 == ROWS, "");
    static_assert(NWN * WN * 8 == COUT, "");
    static_assert(KPSP % KCH == 0, "");

    extern __shared__ __align__(16) __nv_bfloat16 smb[];
    __nv_bfloat16* Ah = smb;
    __nv_bfloat16* Al = Ah + ROWS * KPAD;
    __nv_bfloat16* Bh = Al + ROWS * KPAD;
    __nv_bfloat16* Bl = Bh + COUT * KPAD;
    __shared__ int   s_sidx[INSTS][S];
    __shared__ float s_wk[INSTS];

    const int t    = threadIdx.x;
    const int wid  = t >> 5;
    const int lane = t & 31;
    const int bs   = blockIdx.x;
    const int ksBlk = SPLITK ? (bs / vkTiles) : 0;
    const int vk0   = (SPLITK ? (bs % vkTiles) : bs) * INSTS;

    if (t < INSTS * S) {
        const int i2 = t / S, s = t % S;
        const int vk = vk0 + i2, v = vk / 3, k = vk % 3;
        const int p = didx[v * 3 + k];
        s_sidx[i2][s] = spiral[p * S + s];
        if (s == 0) s_wk[i2] = dw[v * 3 + k];
    }
    __syncthreads();

    float c[WM][WN][4];
#pragma unroll
    for (int mt = 0; mt < WM; ++mt)
#pragma unroll
        for (int nt = 0; nt < WN; ++nt)
#pragma unroll
            for (int i = 0; i < 4; ++i) c[mt][nt][i] = 0.f;

    const int g = lane >> 2, q = lane & 3;
    const int mwIdx = wid / NWN, nwIdx = wid % NWN;
    const int R0 = mwIdx * WM * 16;
    const int N0 = nwIdx * WN * 8;
    const size_t VinCIN = (size_t)Vin * CIN;

    constexpr uint32_t AL_OFF = (uint32_t)(ROWS * KPAD * 2);
    constexpr uint32_t BL_OFF = (uint32_t)(COUT * KPAD * 2);
    const uint32_t aBase = smem_u32(Ah) +
        ((uint32_t)(R0 + (lane & 15)) * KPAD) * 2 + ((uint32_t)(lane >> 4)) * 16;
    const uint32_t bBase = smem_u32(Bh) +
        ((uint32_t)(N0 + (lane & 7)) * KPAD) * 2 + ((uint32_t)((lane >> 3) & 1)) * 16;

    for (int ch = 0; ch < NCH; ++ch) {
        const int k0 = ksBlk * KPSP + ch * KCH;
        // ---- gather A (ROWS x KCH) ----
        if constexpr (CIN == 3) {
            for (int idx = t; idx < ROWS * KCH; idx += 256) {
                const int r = idx & (ROWS - 1), jj = idx / ROWS;
                const int j = k0 + jj;
                __nv_bfloat16 h(0.f), l(0.f);
                if (j < FANR) {
                    const int s = j / 3, ci = j - s * 3;
                    const int inst = r >> 5, b = r & 31;
                    const size_t off = ((size_t)s_sidx[inst][s] * 3 + ci) * 32 + b;
                    h = xh[off]; l = xl[off];
                }
                Ah[r * KPAD + jj] = h;
                Al[r * KPAD + jj] = l;
            }
        } else {
            const int jp = t & 31;
            const int j  = k0 + jp * 2;
            const int s  = j / CIN;
            const int ci = j % CIN;
            for (int r = t >> 5; r < ROWS; r += 8) {
                const int inst = r >> 5, b = r & 31;
                const size_t off = (size_t)b * VinCIN + (size_t)s_sidx[inst][s] * CIN + ci;
                *(uint32_t*)&Ah[r * KPAD + jp * 2] = *(const uint32_t*)&xh[off];
                *(uint32_t*)&Al[r * KPAD + jp * 2] = *(const uint32_t*)&xl[off];
            }
        }
        // ---- stage B (COUT x KCH) from pre-transposed (padded) weights ----
        {
            constexpr int NP = KCH / 2;
            for (int idx = t; idx < COUT * NP; idx += 256) {
                const int jp = idx % NP, n = idx / NP;
                const size_t off = (size_t)n * FANP + k0 + jp * 2;
                *(uint32_t*)&Bh[n * KPAD + jp * 2] = *(const uint32_t*)&wth[off];
                *(uint32_t*)&Bl[n * KPAD + jp * 2] = *(const uint32_t*)&wtl[off];
            }
        }
        __syncthreads();

#pragma unroll
        for (int kk = 0; kk < KCH; kk += 16) {
            const uint32_t kb = (uint32_t)kk * 2;
            uint32_t ah[WM][4], al[WM][4];
#pragma unroll
            for (int mt = 0; mt < WM; ++mt) {
                const uint32_t ad = aBase + (uint32_t)(mt * 16 * KPAD * 2) + kb;
                ldsm_x4(ah[mt], ad);
                ldsm_x4(al[mt], ad + AL_OFF);
            }
#pragma unroll
            for (int nt = 0; nt < WN; ++nt) {
                const uint32_t bd = bBase + (uint32_t)(nt * 8 * KPAD * 2) + kb;
                uint32_t bh[2], bl[2];
                ldsm_x2(bh, bd);
                ldsm_x2(bl, bd + BL_OFF);
#pragma unroll
                for (int mt = 0; mt < WM; ++mt) {
                    mma_bf16(c[mt][nt], ah[mt], bh[0], bh[1]);
                    mma_bf16(c[mt][nt], al[mt], bh[0], bh[1]);
                    mma_bf16(c[mt][nt], ah[mt], bl[0], bl[1]);
                }
            }
        }
        __syncthreads();
    }

    // ---- epilogue: fragment -> gmem partials ----
#pragma unroll
    for (int mt = 0; mt < WM; ++mt) {
        const int rBase = R0 + mt * 16;
        const int inst  = rBase >> 5;
        const int vk    = vk0 + inst;
        const float wk  = s_wk[inst];
        const int rA = rBase + g, rB = rA + 8;
        size_t baseA, baseB;
        if (SPLITK) {
            const size_t vb = ((size_t)vk * KS + ksBlk) * 32;
            baseA = (vb + (rA & 31)) * COUT;
            baseB = (vb + (rB & 31)) * COUT;
        } else {
            baseA = ((size_t)vk * 32 + (rA & 31)) * COUT;
            baseB = ((size_t)vk * 32 + (rB & 31)) * COUT;
        }
#pragma unroll
        for (int nt = 0; nt < WN; ++nt) {
            const int col = N0 + nt * 8 + q * 2;
            float v0 = c[mt][nt][0], v1 = c[mt][nt][1];
            float v2 = c[mt][nt][2], v3 = c[mt][nt][3];
            if (!SPLITK) {
                const float bi0 = bias[col], bi1 = bias[col + 1];
                v0 = wk * elu_f(v0 + bi0); v1 = wk * elu_f(v1 + bi1);
                v2 = wk * elu_f(v2 + bi0); v3 = wk * elu_f(v3 + bi1);
            }
            *(float2*)&part[baseA + col] = make_float2(v0, v1);
            *(float2*)&part[baseB + col] = make_float2(v2, v3);
        }
    }
}

// ---------------------------------------------------------------------------
// Pool-reduce; writes fp32 and/or bf16 hi/lo per flags
// ---------------------------------------------------------------------------
template<int COUT, bool WF32, bool BF>
__global__ void reduce_pool(const float* __restrict__ part,
                            float* __restrict__ xout,
                            __nv_bfloat16* __restrict__ xh,
                            __nv_bfloat16* __restrict__ xl,
                            int Vout, int total4)
{
    const int i = blockIdx.x * 256 + threadIdx.x;
    if (i >= total4) return;
    constexpr int C4 = COUT / 4;
    const int c4 = i % C4;
    const int v  = (i / C4) % Vout;
    const int b  = i / (C4 * Vout);
    const float4* p = (const float4*)part;
    float4 a0 = p[((size_t)(v * 3 + 0) * 32 + b) * C4 + c4];
    float4 a1 = p[((size_t)(v * 3 + 1) * 32 + b) * C4 + c4];
    float4 a2 = p[((size_t)(v * 3 + 2) * 32 + b) * C4 + c4];
    const float4 o = make_float4(a0.x + a1.x + a2.x, a0.y + a1.y + a2.y,
                                 a0.z + a1.z + a2.z, a0.w + a1.w + a2.w);
    const size_t off4 = ((size_t)b * Vout + v) * C4 + c4;
    if constexpr (WF32) ((float4*)xout)[off4] = o;
    if constexpr (BF)   write_bf4(xh, xl, off4 * 4, o);
}

// ---------------------------------------------------------------------------
// K-split reduce: bias + ELU + dw + pool; outputs per flags
// ---------------------------------------------------------------------------
template<int COUT, int KS, bool WF32, bool BF>
__global__ void reduce_split(const float* __restrict__ part,
                             const float* __restrict__ dw,
                             const float* __restrict__ bias,
                             float* __restrict__ xout,
                             __nv_bfloat16* __restrict__ xh,
                             __nv_bfloat16* __restrict__ xl,
                             int Vout, int total4)
{
    const int i = blockIdx.x * 256 + threadIdx.x;
    if (i >= total4) return;
    constexpr int C4 = COUT / 4;
    const int c4 = i % C4;
    const int v  = (i / C4) % Vout;
    const int b  = i / (C4 * Vout);
    const float4* p = (const float4*)part;
    const float4 bs4 = ((const float4*)bias)[c4];
    float4 o = make_float4(0.f, 0.f, 0.f, 0.f);
#pragma unroll
    for (int k = 0; k < 3; ++k) {
        float4 s = bs4;
#pragma unroll
        for (int ks = 0; ks < KS; ++ks) {
            const float4 a = p[(((size_t)(v * 3 + k) * KS + ks) * 32 + b) * C4 + c4];
            s.x += a.x; s.y += a.y; s.z += a.z; s.w += a.w;
        }
        const float wk = dw[v * 3 + k];
        o.x += wk * elu_f(s.x);
        o.y += wk * elu_f(s.y);
        o.z += wk * elu_f(s.z);
        o.w += wk * elu_f(s.w);
    }
    const size_t off4 = ((size_t)b * Vout + v) * C4 + c4;
    if constexpr (WF32) ((float4*)xout)[off4] = o;
    if constexpr (BF)   write_bf4(xh, xl, off4 * 4, o);
}

// ---------------------------------------------------------------------------
// FC1 partial GEMM + reduce + FC2 (round-7, proven)
// ---------------------------------------------------------------------------
__global__ void __launch_bounds__(256, 2) fc1_conv(
    const float* __restrict__ xf, const float* __restrict__ Wl1,
    float* __restrict__ partf)
{
    constexpr int KC = 64, CT = 256, LANES = 64, GSROW = 34;
    extern __shared__ float sm[];
    float* Ws = sm;
    float* xs = sm + KC * CT;

    const int t = threadIdx.x;
    const int tx = t % LANES, pg = t / LANES;
    const int ct0 = blockIdx.x * CT;
    const int k0 = blockIdx.y * 512;

    ull acc[4][4];
#pragma unroll
    for (int ic = 0; ic < 4; ++ic)
#pragma unroll
        for (int ibp = 0; ibp < 4; ++ibp) acc[ic][ibp] = 0ull;

    for (int kc = 0; kc < 512; kc += KC) {
        const int kk0 = k0 + kc;
        for (int i = t; i < KC * CT / 4; i += 256) {
            const int row = i / (CT / 4), col = i % (CT / 4);
            ((float4*)Ws)[i] = *(const float4*)&Wl1[(size_t)(kk0 + row) * 512 + ct0 + col * 4];
        }
#pragma unroll
        for (int e = 0; e < 8; ++e) {
            const int idx = e * 256 + t;
            const int b = idx / KC, jj = idx % KC;
            xs[jj * GSROW + b] = xf[(size_t)b * 32768 + kk0 + jj];
        }
        __syncthreads();

        const float* gb = xs + pg * 8;
#pragma unroll 4
        for (int jj = 0; jj < KC; ++jj) {
            const float4 w4 = *(const float4*)&Ws[jj * CT + tx * 4];
            ull wp[4];
            wp[0] = pack2(w4.x, w4.x);
            wp[1] = pack2(w4.y, w4.y);
            wp[2] = pack2(w4.z, w4.z);
            wp[3] = pack2(w4.w, w4.w);
            ull gp[4];
#pragma unroll
            for (int ibp = 0; ibp < 4; ++ibp)
                gp[ibp] = *(const ull*)&gb[jj * GSROW + 2 * ibp];
#pragma unroll
            for (int ic = 0; ic < 4; ++ic)
#pragma unroll
                for (int ibp = 0; ibp < 4; ++ibp)
                    fma2(acc[ic][ibp], gp[ibp], wp[ic]);
        }
        __syncthreads();
    }

    const size_t base = (size_t)blockIdx.y * 32 * 512 + ct0 + tx * 4;
#pragma unroll
    for (int ibp = 0; ibp < 4; ++ibp) {
        const int b0 = (pg * 4 + ibp) * 2;
        float lo[4], hi[4];
#pragma unroll
        for (int ic = 0; ic < 4; ++ic) unpack2(acc[ic][ibp], lo[ic], hi[ic]);
        *(float4*)&partf[base + (size_t)b0 * 512]       = make_float4(lo[0], lo[1], lo[2], lo[3]);
        *(float4*)&partf[base + (size_t)(b0 + 1) * 512] = make_float4(hi[0], hi[1], hi[2], hi[3]);
    }
}

__global__ void fc1_reduce(const float* __restrict__ partf,
                           const float* __restrict__ bl1,
                           float* __restrict__ h, float* __restrict__ out)
{
    const int i = blockIdx.x * 256 + threadIdx.x;
    if (i < 16384) {
        float s = 0.f;
#pragma unroll
        for (int p = 0; p < 64; ++p) s += partf[p * 16384 + i];
        s += bl1[i & 511];
        s = elu_f(s);
        h[i] = s;
        out[i] = s;
    }
}

__global__ void fc2_kernel(const float* __restrict__ h,
                           const float* __restrict__ Wl2,
                           const float* __restrict__ bl2,
                           float* __restrict__ out)
{
    const int b = blockIdx.x;
    const int c = threadIdx.x;
    float acc = bl2[c];
    for (int k = 0; k < 512; ++k)
        acc = fmaf(h[b * 512 + k], Wl2[k * 64 + c], acc);
    out[16384 + b * 64 + c] = acc;
}

// ---------------------------------------------------------------------------
// Host launcher
// ---------------------------------------------------------------------------
extern "C" void kernel_launch(void* const* d_in, const int* in_sizes, int n_in,
                              void* d_out, int out_size)
{
    int I_sp[4], I_di[4], I_dw[4], I_W[4], I_b[4];
    if (in_sizes[2] == 8192 * 3) {           // dict order
        for (int i = 0; i < 4; ++i) {
            I_sp[i] = 1 + 5 * i; I_di[i] = 2 + 5 * i; I_dw[i] = 3 + 5 * i;
            I_W[i] = 4 + 5 * i;  I_b[i] = 5 + 5 * i;
        }
    } else {                                  // signature order
        for (int i = 0; i < 4; ++i) {
            I_sp[i] = 1 + i; I_di[i] = 5 + i; I_dw[i] = 9 + i;
            I_W[i] = 13 + 2 * i; I_b[i] = 14 + 2 * i;
        }
    }

    const float* x = (const float*)d_in[0];
    const int* sp[4]; const int* di[4]; const float* dwp[4];
    const float* W[4]; const float* b[4];
    for (int i = 0; i < 4; ++i) {
        sp[i]  = (const int*)  d_in[I_sp[i]];
        di[i]  = (const int*)  d_in[I_di[i]];
        dwp[i] = (const float*)d_in[I_dw[i]];
        W[i]   = (const float*)d_in[I_W[i]];
        b[i]   = (const float*)d_in[I_b[i]];
    }
    const float* Wl1 = (const float*)d_in[21];
    const float* bl1 = (const float*)d_in[22];
    const float* Wl2 = (const float*)d_in[23];
    const float* bl2 = (const float*)d_in[24];

    float *x4, *p0, *p1, *p2, *p3, *pf, *h;
    __nv_bfloat16 *x0h, *x0l, *x1h, *x1l, *x2h, *x2l, *x3h, *x3l;
    __nv_bfloat16 *w0h, *w0l, *w1h, *w1l, *w2h, *w2l, *w3h, *w3l;
    cudaGetSymbolAddress((void**)&x4, g_x4);
    cudaGetSymbolAddress((void**)&p0, g_p0);
    cudaGetSymbolAddress((void**)&p1, g_p1);
    cudaGetSymbolAddress((void**)&p2, g_p2);
    cudaGetSymbolAddress((void**)&p3, g_p3);
    cudaGetSymbolAddress((void**)&pf, g_pf);
    cudaGetSymbolAddress((void**)&h,  g_h);
    cudaGetSymbolAddress((void**)&x0h, g_x0h);
    cudaGetSymbolAddress((void**)&x0l, g_x0l);
    cudaGetSymbolAddress((void**)&x1h, g_x1h);
    cudaGetSymbolAddress((void**)&x1l, g_x1l);
    cudaGetSymbolAddress((void**)&x2h, g_x2h);
    cudaGetSymbolAddress((void**)&x2l, g_x2l);
    cudaGetSymbolAddress((void**)&x3h, g_x3h);
    cudaGetSymbolAddress((void**)&x3l, g_x3l);
    cudaGetSymbolAddress((void**)&w0h, g_w0h);
    cudaGetSymbolAddress((void**)&w0l, g_w0l);
    cudaGetSymbolAddress((void**)&w1h, g_w1h);
    cudaGetSymbolAddress((void**)&w1l, g_w1l);
    cudaGetSymbolAddress((void**)&w2h, g_w2h);
    cudaGetSymbolAddress((void**)&w2l, g_w2l);
    cudaGetSymbolAddress((void**)&w3h, g_w3h);
    cudaGetSymbolAddress((void**)&w3l, g_w3l);
    float* out = (float*)d_out;

    // smem bytes: 2*(ROWS*KPAD + COUT*KPAD)*2   (round-14 shapes)
    const int smH0 = 2 * (128 * 56 + 32 * 56) * 2;                // 35840
    const int smH1 = 2 * (128 * 72 + 64 * 72) * 2;                // 55296
    const int smH2 = 2 * (64 * 72 + 128 * 72) * 2;                // 55296
    const int smH3 = 2 * (32 * 72 + 256 * 72) * 2;                // 82944
    const int smf  = (64 * 256 + 64 * 34) * 4;                    // 74240

    cudaFuncSetAttribute(stage_hmma<3, 32, 1, false, 128, 1, 4, 1, 48, 48, 36>,
                         cudaFuncAttributeMaxDynamicSharedMemorySize, smH0);
    cudaFuncSetAttribute(stage_hmma<32, 64, 1, false, 128, 2, 4, 2, 64, 384, 384>,
                         cudaFuncAttributeMaxDynamicSharedMemorySize, smH1);
    cudaFuncSetAttribute(stage_hmma<64, 128, 3, true, 64, 2, 4, 4, 64, 256, 768>,
                         cudaFuncAttributeMaxDynamicSharedMemorySize, smH2);
    cudaFuncSetAttribute(stage_hmma<128, 256, 3, true, 32, 2, 4, 8, 64, 512, 1536>,
                         cudaFuncAttributeMaxDynamicSharedMemorySize, smH3);
    cudaFuncSetAttribute(fc1_conv, cudaFuncAttributeMaxDynamicSharedMemorySize, smf);

    // weight pre-convert (tiled, coalesced)
    conv_wt<36, 48, 32><<<6, 256>>>(W[0], w0h, w0l);
    conv_wt_t<384, 64><<<dim3(12, 2), 256>>>(W[1], w1h, w1l);
    conv_wt_t<768, 128><<<dim3(24, 4), 256>>>(W[2], w2h, w2l);
    conv_wt_t<1536, 256><<<dim3(48, 8), 256>>>(W[3], w3h, w3l);

    transpose_x<<<1024, 256>>>(x, x0h, x0l);

    // stage0 (HMMA): vk=24576, 4 inst/CTA -> 6144 CTAs
    stage_hmma<3, 32, 1, false, 128, 1, 4, 1, 48, 48, 36><<<6144, 256, smH0>>>(
        x0h, x0l, sp[0], di[0], dwp[0], w0h, w0l, b[0], p0, 32768, 6144);
    reduce_pool<32, false, true><<<8192, 256>>>(p0, nullptr, x1h, x1l, 8192, 32 * 8192 * 8);

    // stage1 (HMMA): 1536 tiles
    stage_hmma<32, 64, 1, false, 128, 2, 4, 2, 64, 384, 384><<<1536, 256, smH1>>>(
        x1h, x1l, sp[1], di[1], dwp[1], w1h, w1l, b[1], p1, 8192, 1536);
    reduce_pool<64, false, true><<<4096, 256>>>(p1, nullptr, x2h, x2l, 2048, 32 * 2048 * 16);

    // stage2 (HMMA): 768 tiles x 3 KS = 2304 CTAs
    stage_hmma<64, 128, 3, true, 64, 2, 4, 4, 64, 256, 768><<<2304, 256, smH2>>>(
        x2h, x2l, sp[2], di[2], dwp[2], w2h, w2l, b[2], p2, 2048, 768);
    reduce_split<128, 3, false, true><<<2048, 256>>>(p2, dwp[2], b[2], nullptr, x3h, x3l, 512, 32 * 512 * 32);

    // stage3 (HMMA): 384 tiles x 3 KS = 1152 CTAs
    stage_hmma<128, 256, 3, true, 32, 2, 4, 8, 64, 512, 1536><<<1152, 256, smH3>>>(
        x3h, x3l, sp[3], di[3], dwp[3], w3h, w3l, b[3], p3, 512, 384);
    reduce_split<256, 3, true, false><<<1024, 256>>>(p3, dwp[3], b[3], x4, nullptr, nullptr, 128, 32 * 128 * 64);

    fc1_conv<<<dim3(2, 64), 256, smf>>>(x4, Wl1, pf);
    fc1_reduce<<<64, 256>>>(pf, bl1, h, out);
    fc2_kernel<<<32, 64>>>(h, Wl2, bl2, out);
}